// round 17
// baseline (speedup 1.0000x reference)
#include <cuda_runtime.h>
#include <cuda_bf16.h>
#include <math.h>

#define F 128
#define NHEADS 8
#define SCALE 0.25f            // 1/sqrt(16)
#define MAXN 50048
#define MAXE 640064
#define OFFM (MAXN*NHEADS)
#define PGRID 152               // persistent, 1 CTA/SM

// ---------------- device scratch (static: no allocations allowed) ----------
__device__ float g_q  [MAXN*F];
__device__ float g_v  [MAXN*F];
__device__ float g_Ein[MAXE*NHEADS];
__device__ float g_Eou[MAXE*NHEADS];
__device__ float g_Edg[MAXE*NHEADS];
__device__ float g_att[MAXE];
__device__ float g_D  [3*OFFM];
__device__ float g_Di [3*OFFM];
__device__ float g_S  [OFFM];

// ---------------- helpers ---------------------------------------------------
__device__ __forceinline__ unsigned pack_bf2(float flo, float fhi) {
    unsigned r;
    asm("cvt.rn.satfinite.bf16x2.f32 %0, %1, %2;" : "=r"(r) : "f"(fhi), "f"(flo));
    return r;
}
__device__ __forceinline__ void mma_bf16(float (&c)[4], const unsigned (&a)[4],
                                         const unsigned (&b)[2]) {
    asm volatile("mma.sync.aligned.m16n8k16.row.col.f32.bf16.bf16.f32 "
        "{%0,%1,%2,%3}, {%4,%5,%6,%7}, {%8,%9}, {%0,%1,%2,%3};"
        : "+f"(c[0]), "+f"(c[1]), "+f"(c[2]), "+f"(c[3])
        : "r"(a[0]), "r"(a[1]), "r"(a[2]), "r"(a[3]), "r"(b[0]), "r"(b[1]));
}
__device__ __forceinline__ void barx(int id, int cnt) {
    asm volatile("bar.sync %0, %1;" :: "r"(id), "r"(cnt) : "memory");
}

#define SAW 136
#define TB  (128*SAW*2)          // bytes per 128x128 bf16 tile (34816)
#define KPW 132                  // fp32 k-tile row stride (floats)

template<int NT, bool SCALED>
__device__ __forceinline__ void load_conv(const float* __restrict__ src, int row0, int nrows,
                                          __nv_bfloat16* aHi, __nv_bfloat16* aLo,
                                          int tid, const float* __restrict__ scl) {
    for (int g = tid; g < 2048; g += NT) {
        int row = g >> 4, c8 = (g & 15) << 3;
        float fs[8] = {0.f, 0.f, 0.f, 0.f, 0.f, 0.f, 0.f, 0.f};
        int gr = row0 + row;
        if (gr < nrows) {
            const float4* p = (const float4*)(src + (size_t)gr * 128 + c8);
            float4 f0 = p[0], f1 = p[1];
            fs[0] = f0.x; fs[1] = f0.y; fs[2] = f0.z; fs[3] = f0.w;
            fs[4] = f1.x; fs[5] = f1.y; fs[6] = f1.z; fs[7] = f1.w;
            if (SCALED) {
                float sc = scl[gr * NHEADS + (c8 >> 4)];
#pragma unroll
                for (int j = 0; j < 8; j++) fs[j] *= sc;
            }
        }
        unsigned hi[4], lo[4];
#pragma unroll
        for (int j = 0; j < 4; j++) {
            unsigned h = pack_bf2(fs[2 * j], fs[2 * j + 1]);
            float h0f = __uint_as_float(h << 16);
            float h1f = __uint_as_float(h & 0xFFFF0000u);
            hi[j] = h;
            lo[j] = pack_bf2(fs[2 * j] - h0f, fs[2 * j + 1] - h1f);
        }
        *(uint4*)(aHi + row * SAW + c8) = make_uint4(hi[0], hi[1], hi[2], hi[3]);
        *(uint4*)(aLo + row * SAW + c8) = make_uint4(lo[0], lo[1], lo[2], lo[3]);
    }
}

// 16-warp variant (qv/out): one warp's 16x64 share (R8-validated)
__device__ __forceinline__ void mma_tile(const __nv_bfloat16* aH, const __nv_bfloat16* aL,
                                         const __nv_bfloat16* wH, const __nv_bfloat16* wL,
                                         int lane, int wr, int wc, float (&acc)[8][4]) {
    int qp = (lane & 3) * 2;
    int r0 = wr + (lane >> 2);
#pragma unroll
    for (int nt = 0; nt < 8; nt++)
#pragma unroll
        for (int c = 0; c < 4; c++) acc[nt][c] = 0.f;
#pragma unroll
    for (int ks = 0; ks < 8; ks++) {
        int kc = ks * 16 + qp;
        unsigned aHf[4], aLf[4];
        aHf[0] = *(const unsigned*)(aH + r0 * SAW + kc);
        aHf[1] = *(const unsigned*)(aH + (r0 + 8) * SAW + kc);
        aHf[2] = *(const unsigned*)(aH + r0 * SAW + kc + 8);
        aHf[3] = *(const unsigned*)(aH + (r0 + 8) * SAW + kc + 8);
        aLf[0] = *(const unsigned*)(aL + r0 * SAW + kc);
        aLf[1] = *(const unsigned*)(aL + (r0 + 8) * SAW + kc);
        aLf[2] = *(const unsigned*)(aL + r0 * SAW + kc + 8);
        aLf[3] = *(const unsigned*)(aL + (r0 + 8) * SAW + kc + 8);
#pragma unroll
        for (int nt = 0; nt < 8; nt++) {
            int n = wc + nt * 8 + (lane >> 2);
            unsigned bHf[2], bLf[2];
            bHf[0] = *(const unsigned*)(wH + n * SAW + kc);
            bHf[1] = *(const unsigned*)(wH + n * SAW + kc + 8);
            bLf[0] = *(const unsigned*)(wL + n * SAW + kc);
            bLf[1] = *(const unsigned*)(wL + n * SAW + kc + 8);
            mma_bf16(acc[nt], aHf, bHf);
            mma_bf16(acc[nt], aHf, bLf);
            mma_bf16(acc[nt], aLf, bHf);
        }
    }
}

// shared epilogue item: gathers already in qs/qd; reads kf, writes E + atomics
__device__ __forceinline__ void epi_item(const float* kf, int et, int h, int e,
                                         int d, const float4 (&qs)[4], const float4 (&qd)[4]) {
    const float4* kk = (const float4*)(kf + et * KPW + h * 16);
    float im = 0.f, om = 0.f, dg = 0.f;
#pragma unroll
    for (int t = 0; t < 4; t++) {
        float4 a = qs[t], b = qd[t], c = kk[t];
        im += a.x*c.x + a.y*c.y + a.z*c.z + a.w*c.w;
        om += b.x*c.x + b.y*c.y + b.z*c.z + b.w*c.w;
        dg += a.x*b.x + a.y*b.y + a.z*b.z + a.w*b.w;
    }
    float ein = __expf(im * SCALE), eou = __expf(om * SCALE), edg = __expf(dg * SCALE);
    size_t o = (size_t)e * NHEADS + h;
    g_Ein[o] = ein; g_Eou[o] = eou; g_Edg[o] = edg;
    int idx = d * NHEADS + h;
    atomicAdd(&g_D[idx], ein);
    atomicAdd(&g_D[OFFM + idx], eou);
    atomicAdd(&g_D[2 * OFFM + idx], edg);
}

// ---------------- smem layouts (byte offsets) -------------------------------
#define K_WH 0
#define K_WL TB
#define K_AH (2*TB)
#define K_AL (3*TB)
#define K_KF (4*TB)
#define K_SB (K_KF + 128*KPW*4)
#define K_SMEM (K_SB + 512)
#define QV_WQH 0
#define QV_WQL TB
#define QV_WVH (2*TB)
#define QV_WVL (3*TB)
#define QV_AH  (4*TB)
#define QV_AL  (5*TB)
#define QV_SBQ (6*TB)
#define QV_SBV (QV_SBQ + 512)
#define QV_SMEM (QV_SBV + 512)
#define O_WH 0
#define O_WL TB
#define O_AH (2*TB)
#define O_AL (3*TB)
#define O_SB (4*TB)
#define O_SMEM (O_SB + 512)

// ---------------- kernels ---------------------------------------------------

__global__ void __launch_bounds__(512, 1) qv_tc_kernel(const float* __restrict__ node_h,
        const float* __restrict__ Wq, const float* __restrict__ bq,
        const float* __restrict__ Wv, const float* __restrict__ bv, int N) {
    extern __shared__ char sm[];
    int tid = threadIdx.x, wid = tid >> 5, lane = tid & 31;
    __nv_bfloat16* WqH = (__nv_bfloat16*)(sm + QV_WQH);
    __nv_bfloat16* WqL = (__nv_bfloat16*)(sm + QV_WQL);
    __nv_bfloat16* WvH = (__nv_bfloat16*)(sm + QV_WVH);
    __nv_bfloat16* WvL = (__nv_bfloat16*)(sm + QV_WVL);
    __nv_bfloat16* AH  = (__nv_bfloat16*)(sm + QV_AH);
    __nv_bfloat16* AL  = (__nv_bfloat16*)(sm + QV_AL);
    float* sBq = (float*)(sm + QV_SBQ);
    float* sBv = (float*)(sm + QV_SBV);
    load_conv<512, false>(Wq, 0, 128, WqH, WqL, tid, nullptr);
    load_conv<512, false>(Wv, 0, 128, WvH, WvL, tid, nullptr);
    if (tid < 128) { sBq[tid] = bq[tid]; sBv[tid] = bv[tid]; }
    __syncthreads();
    int wr = (wid >> 1) << 4, wc = (wid & 1) << 6;
    int qp = (lane & 3) * 2;
    int ntiles = (N + 127) >> 7;
    for (int tile = blockIdx.x; tile < ntiles; tile += gridDim.x) {
        int row0 = tile << 7;
        load_conv<512, false>(node_h, row0, N, AH, AL, tid, nullptr);
        __syncthreads();
        float acc[8][4];
        mma_tile(AH, AL, WqH, WqL, lane, wr, wc, acc);
        {
            int r = wr + (lane >> 2);
            int gr0 = row0 + r, gr1 = gr0 + 8;
#pragma unroll
            for (int nt = 0; nt < 8; nt++) {
                int col = wc + nt * 8 + qp;
                if (gr0 < N) *(float2*)(g_q + (size_t)gr0 * 128 + col) =
                    make_float2(acc[nt][0] + sBq[col], acc[nt][1] + sBq[col + 1]);
                if (gr1 < N) *(float2*)(g_q + (size_t)gr1 * 128 + col) =
                    make_float2(acc[nt][2] + sBq[col], acc[nt][3] + sBq[col + 1]);
            }
        }
        mma_tile(AH, AL, WvH, WvL, lane, wr, wc, acc);
        {
            int r = wr + (lane >> 2);
            int gr0 = row0 + r, gr1 = gr0 + 8;
#pragma unroll
            for (int nt = 0; nt < 8; nt++) {
                int col = wc + nt * 8 + qp;
                if (gr0 < N) *(float2*)(g_v + (size_t)gr0 * 128 + col) =
                    make_float2(acc[nt][0] + sBv[col], acc[nt][1] + sBv[col + 1]);
                if (gr1 < N) *(float2*)(g_v + (size_t)gr1 * 128 + col) =
                    make_float2(acc[nt][2] + sBv[col], acc[nt][3] + sBv[col + 1]);
            }
        }
        __syncthreads();
    }
}

// warp-specialized + rebalanced:
//   warps 0-7  (256 thr): A-load + GEMM (32r x 64c each) + kf write + 1 epilogue
//                         item (edges 0..31)
//   warps 8-15 (256 thr): 3 epilogue items (edges 32..127), q-gathers
//                         double-buffered, item 0 prefetched before the barrier
// named barriers: 1 = kf full (512), 2 = kf free (512), 3 = A ready (256)
__global__ void __launch_bounds__(512, 1) k_logits_tc_kernel(const float* __restrict__ edge_h,
        const float* __restrict__ Wk, const float* __restrict__ bk,
        const int* __restrict__ src, const int* __restrict__ dst, int E) {
    extern __shared__ char sm[];
    int tid = threadIdx.x, wid = tid >> 5, lane = tid & 31;
    __nv_bfloat16* WH = (__nv_bfloat16*)(sm + K_WH);
    __nv_bfloat16* WL = (__nv_bfloat16*)(sm + K_WL);
    __nv_bfloat16* AH = (__nv_bfloat16*)(sm + K_AH);
    __nv_bfloat16* AL = (__nv_bfloat16*)(sm + K_AL);
    float* kf = (float*)(sm + K_KF);
    float* sB = (float*)(sm + K_SB);
    load_conv<512, false>(Wk, 0, 128, WH, WL, tid, nullptr);
    if (tid < 128) sB[tid] = bk[tid];
    __syncthreads();
    int ntiles = (E + 127) >> 7;

    if (wid < 8) {
        // ------------- producers: GEMM (4 row-groups x 2 col-groups) + 1 item
        int wrg = wid >> 1, wcg = wid & 1;
        int qp = (lane & 3) * 2;
        int r0 = wrg * 32 + (lane >> 2);
        int nbase = wcg * 64;
        int pet = tid >> 3, ph = tid & 7;     // producer epilogue item: edges 0..31
        for (int tile = blockIdx.x; tile < ntiles; tile += gridDim.x) {
            int row0 = tile << 7;
            load_conv<256, false>(edge_h, row0, E, AH, AL, tid, nullptr);
            int pe = row0 + pet;
            bool pv = pe < E;
            int psi = 0, pdi = 0;
            if (pv) { psi = __ldg(src + pe); pdi = __ldg(dst + pe); }
            barx(3, 256);                  // A tile ready
            float acc[2][8][4];
#pragma unroll
            for (int st = 0; st < 2; st++)
#pragma unroll
                for (int nt = 0; nt < 8; nt++)
#pragma unroll
                    for (int c = 0; c < 4; c++) acc[st][nt][c] = 0.f;
#pragma unroll
            for (int ks = 0; ks < 8; ks++) {
                int kc = ks * 16 + qp;
                unsigned aHf[2][4], aLf[2][4];
#pragma unroll
                for (int st = 0; st < 2; st++) {
                    int rr = r0 + st * 16;
                    aHf[st][0] = *(const unsigned*)(AH + rr * SAW + kc);
                    aHf[st][1] = *(const unsigned*)(AH + (rr + 8) * SAW + kc);
                    aHf[st][2] = *(const unsigned*)(AH + rr * SAW + kc + 8);
                    aHf[st][3] = *(const unsigned*)(AH + (rr + 8) * SAW + kc + 8);
                    aLf[st][0] = *(const unsigned*)(AL + rr * SAW + kc);
                    aLf[st][1] = *(const unsigned*)(AL + (rr + 8) * SAW + kc);
                    aLf[st][2] = *(const unsigned*)(AL + rr * SAW + kc + 8);
                    aLf[st][3] = *(const unsigned*)(AL + (rr + 8) * SAW + kc + 8);
                }
#pragma unroll
                for (int nt = 0; nt < 8; nt++) {
                    int n = nbase + nt * 8 + (lane >> 2);
                    unsigned bHf[2], bLf[2];
                    bHf[0] = *(const unsigned*)(WH + n * SAW + kc);
                    bHf[1] = *(const unsigned*)(WH + n * SAW + kc + 8);
                    bLf[0] = *(const unsigned*)(WL + n * SAW + kc);
                    bLf[1] = *(const unsigned*)(WL + n * SAW + kc + 8);
#pragma unroll
                    for (int st = 0; st < 2; st++) {
                        mma_bf16(acc[st][nt], aHf[st], bHf);
                        mma_bf16(acc[st][nt], aHf[st], bLf);
                        mma_bf16(acc[st][nt], aLf[st], bHf);
                    }
                }
            }
            barx(2, 512);                  // kf free (prev consumers + own reads done)
#pragma unroll
            for (int st = 0; st < 2; st++) {
                int rr = r0 + st * 16;
#pragma unroll
                for (int nt = 0; nt < 8; nt++) {
                    int col = nbase + nt * 8 + qp;
                    *(float2*)(kf + rr * KPW + col) =
                        make_float2(acc[st][nt][0] + sB[col], acc[st][nt][1] + sB[col + 1]);
                    *(float2*)(kf + (rr + 8) * KPW + col) =
                        make_float2(acc[st][nt][2] + sB[col], acc[st][nt][3] + sB[col + 1]);
                }
            }
            barx(1, 512);                  // kf full
            // ---- producer epilogue item (edges 0..31) ----
            if (pv) {
                float4 qs[4], qd[4];
                const float4* ps = (const float4*)(g_q + (size_t)psi * 128 + ph * 16);
                const float4* pd = (const float4*)(g_q + (size_t)pdi * 128 + ph * 16);
#pragma unroll
                for (int t = 0; t < 4; t++) { qs[t] = ps[t]; qd[t] = pd[t]; }
                epi_item(kf, pet, ph, pe, pdi, qs, qd);
            }
        }
    } else {
        // -------- consumers: 3 items (edges 32..127), double-buffered gathers
        int j  = tid - 256;
        int h  = j & 7;
        int eb = 32 + (j >> 3);            // 32..63; items at eb, eb+32, eb+64
        for (int tile = blockIdx.x; tile < ntiles; tile += gridDim.x) {
            int row0 = tile << 7;
            int ee[3], ss[3], dd[3]; bool vv[3];
#pragma unroll
            for (int i = 0; i < 3; i++) {
                ee[i] = row0 + eb + 32 * i;
                vv[i] = ee[i] < E;
                ss[i] = 0; dd[i] = 0;
                if (vv[i]) { ss[i] = __ldg(src + ee[i]); dd[i] = __ldg(dst + ee[i]); }
            }
            // prefetch item 0's gathers (independent of kf)
            float4 qsb[2][4], qdb[2][4];
            if (vv[0]) {
                const float4* ps = (const float4*)(g_q + (size_t)ss[0] * 128 + h * 16);
                const float4* pd = (const float4*)(g_q + (size_t)dd[0] * 128 + h * 16);
#pragma unroll
                for (int t = 0; t < 4; t++) { qsb[0][t] = ps[t]; qdb[0][t] = pd[t]; }
            }
            barx(2, 512);                  // kf free (our prev-tile reads done)
            barx(1, 512);                  // kf full
#pragma unroll
            for (int i = 0; i < 3; i++) {
                if (i < 2 && vv[i + 1]) {  // issue next item's gathers first
                    const float4* ps = (const float4*)(g_q + (size_t)ss[i + 1] * 128 + h * 16);
                    const float4* pd = (const float4*)(g_q + (size_t)dd[i + 1] * 128 + h * 16);
#pragma unroll
                    for (int t = 0; t < 4; t++) {
                        qsb[(i + 1) & 1][t] = ps[t];
                        qdb[(i + 1) & 1][t] = pd[t];
                    }
                }
                if (vv[i])
                    epi_item(kf, eb + 32 * i, h, ee[i], dd[i], qsb[i & 1], qdb[i & 1]);
            }
        }
    }
}

__global__ void __launch_bounds__(512, 1) out_tc_kernel(const float* __restrict__ Wo,
        const float* __restrict__ bo, float* __restrict__ out, int N) {
    extern __shared__ char sm[];
    int tid = threadIdx.x, wid = tid >> 5, lane = tid & 31;
    __nv_bfloat16* WH = (__nv_bfloat16*)(sm + O_WH);
    __nv_bfloat16* WL = (__nv_bfloat16*)(sm + O_WL);
    __nv_bfloat16* AH = (__nv_bfloat16*)(sm + O_AH);
    __nv_bfloat16* AL = (__nv_bfloat16*)(sm + O_AL);
    float* sB = (float*)(sm + O_SB);
    load_conv<512, false>(Wo, 0, 128, WH, WL, tid, nullptr);
    if (tid < 128) sB[tid] = bo[tid];
    __syncthreads();
    int wr = (wid >> 1) << 4, wc = (wid & 1) << 6;
    int qp = (lane & 3) * 2;
    int ntiles = (N + 127) >> 7;
    for (int tile = blockIdx.x; tile < ntiles; tile += gridDim.x) {
        int row0 = tile << 7;
        load_conv<512, true>(g_v, row0, N, AH, AL, tid, g_S);
        __syncthreads();
        float acc[8][4];
        mma_tile(AH, AL, WH, WL, lane, wr, wc, acc);
        {
            int r = wr + (lane >> 2);
            int gr0 = row0 + r, gr1 = gr0 + 8;
#pragma unroll
            for (int nt = 0; nt < 8; nt++) {
                int col = wc + nt * 8 + qp;
                float x0 = acc[nt][0] + sB[col],   x1 = acc[nt][1] + sB[col + 1];
                float x2 = acc[nt][2] + sB[col],   x3 = acc[nt][3] + sB[col + 1];
                x0 = (x0 > 0.f) ? x0 : 0.1f * x0;  x1 = (x1 > 0.f) ? x1 : 0.1f * x1;
                x2 = (x2 > 0.f) ? x2 : 0.1f * x2;  x3 = (x3 > 0.f) ? x3 : 0.1f * x3;
                if (gr0 < N) *(float2*)(out + (size_t)gr0 * 128 + col) = make_float2(x0, x1);
                if (gr1 < N) *(float2*)(out + (size_t)gr1 * 128 + col) = make_float2(x2, x3);
            }
        }
        __syncthreads();
    }
}

__global__ void init_d_kernel(int n) {
    int t = blockIdx.x * blockDim.x + threadIdx.x;
    if (t < 3 * OFFM) g_D[t] = 0.f;
    if (t < OFFM) g_S[t] = 0.f;
}

__global__ void init_att_kernel(const float* __restrict__ dist,
                                const float* __restrict__ lam, int E) {
    int t = blockIdx.x * blockDim.x + threadIdx.x;
    if (t < E) g_att[t] = __powf(dist[t], lam[0]);
}

__global__ void recip_kernel(int N) {
    int t = blockIdx.x * blockDim.x + threadIdx.x;
    if (t >= N * NHEADS) return;
#pragma unroll
    for (int k = 0; k < 3; k++) {
        float d = g_D[k * OFFM + t];
        g_Di[k * OFFM + t] = (d != 0.f) ? 1.f / d : 0.f;
    }
}

__global__ void score_kernel(const int* __restrict__ dst, int E) {
    int t = blockIdx.x * blockDim.x + threadIdx.x;
    if (t >= E * NHEADS) return;
    int e = t >> 3, h = t & 7;
    int idx = dst[e] * NHEADS + h;
    float s = g_Ein[t] * g_Di[idx]
            + g_Eou[t] * g_Di[OFFM + idx]
            + g_Edg[t] * g_Di[2 * OFFM + idx];
    atomicAdd(&g_S[idx], s * g_att[e]);
}

// ---------------- launch -----------------------------------------------------
extern "C" void kernel_launch(void* const* d_in, const int* in_sizes, int n_in,
                              void* d_out, int out_size) {
    const float* node_h   = (const float*)d_in[0];
    const float* edge_h   = (const float*)d_in[1];
    const float* distance = (const float*)d_in[2];
    const float* Wq = (const float*)d_in[3];  const float* bq = (const float*)d_in[4];
    const float* Wk = (const float*)d_in[5];  const float* bk = (const float*)d_in[6];
    const float* Wv = (const float*)d_in[7];  const float* bv = (const float*)d_in[8];
    const float* Wo = (const float*)d_in[9];  const float* bo = (const float*)d_in[10];
    const float* lam = (const float*)d_in[11];
    const int*   src = (const int*)d_in[12];
    const int*   dst = (const int*)d_in[13];

    int N = in_sizes[0] / F;
    int E = in_sizes[12];
    float* out = (float*)d_out;

    cudaFuncSetAttribute(qv_tc_kernel, cudaFuncAttributeMaxDynamicSharedMemorySize, QV_SMEM);
    cudaFuncSetAttribute(k_logits_tc_kernel, cudaFuncAttributeMaxDynamicSharedMemorySize, K_SMEM);
    cudaFuncSetAttribute(out_tc_kernel, cudaFuncAttributeMaxDynamicSharedMemorySize, O_SMEM);

    // launch order keeps k_logits 4th (the slot ncu captures)
    int ib = (3 * OFFM + 255) / 256;
    init_d_kernel<<<ib, 256>>>(0);
    init_att_kernel<<<(E + 255) / 256, 256>>>(distance, lam, E);

    qv_tc_kernel<<<PGRID, 512, QV_SMEM>>>(node_h, Wq, bq, Wv, bv, N);

    k_logits_tc_kernel<<<PGRID, 512, K_SMEM>>>(edge_h, Wk, bk, src, dst, E);

    int tb = (E * NHEADS + 255) / 256;
    int db = (N * NHEADS + 255) / 256;
    recip_kernel<<<db, 256>>>(N);
    score_kernel<<<tb, 256>>>(dst, E);

    out_tc_kernel<<<PGRID, 512, O_SMEM>>>(Wo, bo, out, N);
}